// round 2
// baseline (speedup 1.0000x reference)
#include <cuda_runtime.h>
#include <cuda_bf16.h>
#include <math.h>

// Problem constants (fixed by the dataset)
#define NS 100000
#define NE 100000
#define EDG 1600000
#define D 256
#define H 8
#define HD 32
#define FEAT 64
#define DFF 512

#define SCAN_B 1024
#define NBLK ((NS + SCAN_B - 1) / SCAN_B)   // 98

// ---------------- device scratch (no allocations allowed) ----------------
__device__ float g_z[(size_t)NE * D];     // e-node per-head projections [NE, 256]
__device__ float g_df[(size_t)NS * D];    // dst-feat projections       [NS, 256]
__device__ float g_h[(size_t)NS * D];     // attention output (post-ELU)[NS, 256]
__device__ float g_x[(size_t)NS * D];     // proj output (residual src) [NS, 256]
__device__ float g_xn[(size_t)NS * D];    // layernorm output           [NS, 256]
__device__ float g_t[(size_t)NS * DFF];   // ffn hidden                 [NS, 512]
__device__ float g_score[(size_t)EDG * H];// per-edge scores / exp weights
__device__ float g_Wz[D * D];             // repacked fc_w      [256,256]
__device__ float g_Wd[FEAT * D];          // repacked dstfeat_w [64,256]
__device__ int   g_counts[NS];
__device__ int   g_offsets[NS + 1];
__device__ int   g_cursor[NS];
__device__ int   g_csr_src[EDG];
__device__ int   g_csr_dst[EDG];
__device__ int   g_bsum[NBLK];

// ---------------- small helpers ----------------
__device__ __forceinline__ float gelu_tanh(float x) {
    const float c = 0.7978845608028654f;
    float x3 = x * x * x;
    float t = tanhf(c * (x + 0.044715f * x3));
    return 0.5f * x * (1.0f + t);
}

// ---------------- weight repack: (H, K, HD) -> [K, H*HD] ----------------
__global__ void repack_w(const float* __restrict__ w, float* __restrict__ out, int K) {
    int idx = blockIdx.x * blockDim.x + threadIdx.x;
    if (idx >= K * 256) return;
    int k = idx >> 8;
    int n = idx & 255;
    out[idx] = w[(n >> 5) * (K * 32) + k * 32 + (n & 31)];
}

// ---------------- generic fp32 SGEMM: C = act(A @ B + bias) + res ----------------
template <int ACT, bool HAS_BIAS, bool HAS_RES>
__global__ void __launch_bounds__(256) sgemm_k(
    const float* __restrict__ A0, int lda0,
    const float* __restrict__ A1, int lda1, int ksplit,
    const float* __restrict__ B,
    const float* __restrict__ bias,
    const float* __restrict__ res, int ldr,
    float* __restrict__ C,
    int M, int N, int K)
{
    __shared__ float As[8][132];
    __shared__ float Bs[8][128];

    int t  = threadIdx.x;
    int m0 = blockIdx.y * 128;
    int n0 = blockIdx.x * 128;
    int tx = t & 15;
    int ty = t >> 4;

    int a_m = t >> 1;
    int a_k = (t & 1) * 4;
    int b_k = t >> 5;
    int b_n = (t & 31) * 4;

    float acc[8][8];
#pragma unroll
    for (int i = 0; i < 8; i++)
#pragma unroll
        for (int j = 0; j < 8; j++) acc[i][j] = 0.0f;

    for (int k0 = 0; k0 < K; k0 += 8) {
        int gm = m0 + a_m;
        float4 av = make_float4(0.f, 0.f, 0.f, 0.f);
        if (gm < M) {
            int kk = k0 + a_k;
            const float* p = (kk < ksplit)
                                 ? (A0 + (size_t)gm * lda0 + kk)
                                 : (A1 + (size_t)gm * lda1 + (kk - ksplit));
            av = *(const float4*)p;
        }
        As[a_k + 0][a_m] = av.x;
        As[a_k + 1][a_m] = av.y;
        As[a_k + 2][a_m] = av.z;
        As[a_k + 3][a_m] = av.w;

        float4 bv = *(const float4*)(B + (size_t)(k0 + b_k) * N + n0 + b_n);
        *(float4*)&Bs[b_k][b_n] = bv;

        __syncthreads();

#pragma unroll
        for (int kk = 0; kk < 8; kk++) {
            float a[8], b[8];
            *(float4*)(a)     = *(const float4*)&As[kk][ty * 8];
            *(float4*)(a + 4) = *(const float4*)&As[kk][ty * 8 + 4];
            *(float4*)(b)     = *(const float4*)&Bs[kk][tx * 8];
            *(float4*)(b + 4) = *(const float4*)&Bs[kk][tx * 8 + 4];
#pragma unroll
            for (int i = 0; i < 8; i++)
#pragma unroll
                for (int j = 0; j < 8; j++) acc[i][j] += a[i] * b[j];
        }
        __syncthreads();
    }

#pragma unroll
    for (int i = 0; i < 8; i++) {
        int m = m0 + ty * 8 + i;
        if (m >= M) continue;
#pragma unroll
        for (int jv = 0; jv < 2; jv++) {
            int n = n0 + tx * 8 + jv * 4;
            float4 v;
            float* vp = &v.x;
#pragma unroll
            for (int j = 0; j < 4; j++) {
                float val = acc[i][jv * 4 + j];
                if (HAS_BIAS) val += bias[n + j];
                if (ACT == 1) val = gelu_tanh(val);
                vp[j] = val;
            }
            if (HAS_RES) {
                float4 r = *(const float4*)(res + (size_t)m * ldr + n);
                v.x += r.x; v.y += r.y; v.z += r.z; v.w += r.w;
            }
            *(float4*)(C + (size_t)m * N + n) = v;
        }
    }
}

// ---------------- CSR build ----------------
__global__ void zero_counts() {
    int i = blockIdx.x * blockDim.x + threadIdx.x;
    if (i < NS) g_counts[i] = 0;
}

__global__ void hist_kernel(const int* __restrict__ edge_dst) {
    int i = blockIdx.x * blockDim.x + threadIdx.x;
    if (i < EDG) atomicAdd(&g_counts[edge_dst[i]], 1);
}

// pass1: per-block sums of g_counts
__global__ void __launch_bounds__(SCAN_B) scan_pass1() {
    __shared__ int ws[32];
    int b = blockIdx.x, t = threadIdx.x;
    int i = b * SCAN_B + t;
    int v = (i < NS) ? g_counts[i] : 0;
#pragma unroll
    for (int o = 16; o; o >>= 1) v += __shfl_xor_sync(0xFFFFFFFFu, v, o);
    if ((t & 31) == 0) ws[t >> 5] = v;
    __syncthreads();
    if (t < 32) {
        int x = ws[t];
#pragma unroll
        for (int o = 16; o; o >>= 1) x += __shfl_xor_sync(0xFFFFFFFFu, x, o);
        if (t == 0) g_bsum[b] = x;
    }
}

// pass2: exclusive scan of the NBLK block sums (single block)
__global__ void scan_pass2() {
    __shared__ int sh[128];
    int t = threadIdx.x;
    int orig = (t < NBLK) ? g_bsum[t] : 0;
    sh[t] = orig;
    __syncthreads();
    for (int o = 1; o < 128; o <<= 1) {
        int v = (t >= o) ? sh[t - o] : 0;
        __syncthreads();
        sh[t] += v;
        __syncthreads();
    }
    if (t < NBLK) g_bsum[t] = sh[t] - orig;  // exclusive
}

// pass3: intra-block inclusive scan + block offset -> offsets & cursor
__global__ void __launch_bounds__(SCAN_B) scan_pass3() {
    __shared__ int ws[32];
    int b = blockIdx.x, t = threadIdx.x;
    int lane = t & 31, w = t >> 5;
    int i = b * SCAN_B + t;
    int v = (i < NS) ? g_counts[i] : 0;
    int x = v;
#pragma unroll
    for (int o = 1; o < 32; o <<= 1) {
        int y = __shfl_up_sync(0xFFFFFFFFu, x, o);
        if (lane >= o) x += y;
    }
    if (lane == 31) ws[w] = x;
    __syncthreads();
    if (w == 0) {
        int sv = ws[lane];
#pragma unroll
        for (int o = 1; o < 32; o <<= 1) {
            int y = __shfl_up_sync(0xFFFFFFFFu, sv, o);
            if (lane >= o) sv += y;
        }
        ws[lane] = sv;
    }
    __syncthreads();
    int incl = x + (w > 0 ? ws[w - 1] : 0) + g_bsum[b];
    if (i < NS) {
        g_offsets[i + 1] = incl;
        g_cursor[i] = incl - v;
    }
    if (b == 0 && t == 0) g_offsets[0] = 0;
}

__global__ void scatter_kernel(const int* __restrict__ edge_src,
                               const int* __restrict__ edge_dst) {
    int i = blockIdx.x * blockDim.x + threadIdx.x;
    if (i >= EDG) return;
    int dst = edge_dst[i];
    int pos = atomicAdd(&g_cursor[dst], 1);
    g_csr_src[pos] = edge_src[i];
    g_csr_dst[pos] = dst;
}

// ---------------- phase 1: per-(edge,head) scores, no shuffles ----------------
// block = 256 threads = 32 edges x 8 heads; thread owns one (edge, head) dot.
__global__ void __launch_bounds__(256) score_kernel() {
    __shared__ int s_src[32];
    __shared__ int s_dst[32];
    int base = blockIdx.x * 32;
    int t = threadIdx.x;
    if (t < 32) s_src[t] = g_csr_src[base + t];
    else if (t < 64) s_dst[t - 32] = g_csr_dst[base + t - 32];
    __syncthreads();
    int el = t >> 3, h = t & 7;
    int src = s_src[el], dst = s_dst[el];
    const float4* zp = (const float4*)(g_z + (size_t)src * 256 + h * 32);
    const float4* dp = (const float4*)(g_df + (size_t)dst * 256 + h * 32);
    float acc = 0.0f;
#pragma unroll
    for (int i = 0; i < 8; i++) {
        float4 a = zp[i];
        float4 b = dp[i];
        acc += a.x * b.x + a.y * b.y + a.z * b.z + a.w * b.w;
    }
    g_score[(size_t)base * 8 + t] = acc;
}

// ---------------- phase 2: warp per dst: softmax + weighted aggregation ----------------
__global__ void __launch_bounds__(256) agg_kernel() {
    int gw = (blockIdx.x * blockDim.x + threadIdx.x) >> 5;
    if (gw >= NS) return;
    int lane = threadIdx.x & 31;
    int beg = g_offsets[gw];
    int end = g_offsets[gw + 1];
    int h8 = lane & 7;   // head this lane tracks in passes 1-2
    int eo = lane >> 3;  // edge sub-offset (4 edges per iteration)

    // pass A: per-head max
    float m = -1e30f;
    for (int e = beg + eo; e < end; e += 4)
        m = fmaxf(m, g_score[(size_t)e * 8 + h8]);
    m = fmaxf(m, __shfl_xor_sync(0xFFFFFFFFu, m, 8));
    m = fmaxf(m, __shfl_xor_sync(0xFFFFFFFFu, m, 16));

    // pass B: exp + denom; write exp weights back in place
    float den = 0.0f;
    for (int e = beg + eo; e < end; e += 4) {
        float ex = __expf(g_score[(size_t)e * 8 + h8] - m);
        g_score[(size_t)e * 8 + h8] = ex;
        den += ex;
    }
    den += __shfl_xor_sync(0xFFFFFFFFu, den, 8);
    den += __shfl_xor_sync(0xFFFFFFFFu, den, 16);
    float inv = 1.0f / den;
    __syncwarp();  // make pass-B stores visible to all lanes' loads below

    // pass C: weighted gather-accumulate (no shuffles, no exp)
    float acc[8];
#pragma unroll
    for (int r = 0; r < 8; r++) acc[r] = 0.0f;
    for (int e = beg; e < end; e++) {
        int src = g_csr_src[e];
        const float* zp = g_z + (size_t)src * 256;
        const float* wp = g_score + (size_t)e * 8;
        float exv[8];
#pragma unroll
        for (int r = 0; r < 8; r++) exv[r] = wp[r];  // broadcast loads
#pragma unroll
        for (int r = 0; r < 8; r++) acc[r] += exv[r] * zp[r * 32 + lane];
    }

    float* hp = g_h + (size_t)gw * 256;
#pragma unroll
    for (int r = 0; r < 8; r++) {
        float invr = __shfl_sync(0xFFFFFFFFu, inv, r);  // lane r holds head r's inv
        float v = acc[r] * invr;
        v = (v > 0.0f) ? v : expm1f(v);  // ELU(alpha=1)
        hp[r * 32 + lane] = v;
    }
}

// ---------------- layernorm: one warp per row ----------------
__global__ void ln_kernel(const float* __restrict__ x,
                          const float* __restrict__ gam,
                          const float* __restrict__ bet,
                          float* __restrict__ y) {
    int row = (blockIdx.x * blockDim.x + threadIdx.x) >> 5;
    if (row >= NS) return;
    int lane = threadIdx.x & 31;
    const float* xp = x + (size_t)row * 256;
    float v[8];
    float s = 0.0f, s2 = 0.0f;
#pragma unroll
    for (int r = 0; r < 8; r++) {
        v[r] = xp[r * 32 + lane];
        s += v[r];
        s2 += v[r] * v[r];
    }
#pragma unroll
    for (int off = 16; off > 0; off >>= 1) {
        s  += __shfl_xor_sync(0xFFFFFFFFu, s, off);
        s2 += __shfl_xor_sync(0xFFFFFFFFu, s2, off);
    }
    float mean = s * (1.0f / 256.0f);
    float var = s2 * (1.0f / 256.0f) - mean * mean;
    float inv = rsqrtf(var + 1e-6f);
    float* yp = y + (size_t)row * 256;
#pragma unroll
    for (int r = 0; r < 8; r++) {
        int c = r * 32 + lane;
        yp[c] = (v[r] - mean) * inv * gam[c] + bet[c];
    }
}

// ---------------- launch ----------------
extern "C" void kernel_launch(void* const* d_in, const int* in_sizes, int n_in,
                              void* d_out, int out_size) {
    const float* s_in      = (const float*)d_in[0];
    const float* e_in      = (const float*)d_in[1];
    const float* dst_feat  = (const float*)d_in[2];
    const float* fc_w      = (const float*)d_in[3];
    const float* dstfeat_w = (const float*)d_in[4];
    const float* proj_w    = (const float*)d_in[5];
    const float* proj_b    = (const float*)d_in[6];
    const float* ln_g      = (const float*)d_in[7];
    const float* ln_b      = (const float*)d_in[8];
    const float* w1        = (const float*)d_in[9];
    const float* b1        = (const float*)d_in[10];
    const float* w2        = (const float*)d_in[11];
    const float* b2        = (const float*)d_in[12];
    const int*   edge_src  = (const int*)d_in[13];
    const int*   edge_dst  = (const int*)d_in[14];
    float* out = (float*)d_out;

    float *zp, *dfp, *hp, *xp, *xnp, *tp, *wzp, *wdp;
    cudaGetSymbolAddress((void**)&zp,  g_z);
    cudaGetSymbolAddress((void**)&dfp, g_df);
    cudaGetSymbolAddress((void**)&hp,  g_h);
    cudaGetSymbolAddress((void**)&xp,  g_x);
    cudaGetSymbolAddress((void**)&xnp, g_xn);
    cudaGetSymbolAddress((void**)&tp,  g_t);
    cudaGetSymbolAddress((void**)&wzp, g_Wz);
    cudaGetSymbolAddress((void**)&wdp, g_Wd);

    const int TB = 256;
    dim3 gB(2, (NS + 127) / 128);

    // 1) repack per-head weights into plain [K, 256] matrices
    repack_w<<<(D * 256 + TB - 1) / TB, TB>>>(fc_w, wzp, D);
    repack_w<<<(FEAT * 256 + TB - 1) / TB, TB>>>(dstfeat_w, wdp, FEAT);

    // 2) z = e @ Wz  [NE,256]
    sgemm_k<0, false, false><<<dim3(2, (NE + 127) / 128), TB>>>(
        e_in, D, e_in, D, D, wzp, nullptr, nullptr, 0, zp, NE, 256, D);

    // 3) df = dst_feat @ Wd  [NS,256]
    sgemm_k<0, false, false><<<gB, TB>>>(
        dst_feat, FEAT, dst_feat, FEAT, FEAT, wdp, nullptr, nullptr, 0, dfp, NS, 256, FEAT);

    // 4) CSR build by dst (parallel decoupled scan)
    zero_counts<<<(NS + TB - 1) / TB, TB>>>();
    hist_kernel<<<(EDG + TB - 1) / TB, TB>>>(edge_dst);
    scan_pass1<<<NBLK, SCAN_B>>>();
    scan_pass2<<<1, 128>>>();
    scan_pass3<<<NBLK, SCAN_B>>>();
    scatter_kernel<<<(EDG + TB - 1) / TB, TB>>>(edge_src, edge_dst);

    // 5) attention: scores (edge-parallel), then softmax+aggregate (warp/dst)
    score_kernel<<<EDG / 32, 256>>>();
    agg_kernel<<<(NS * 32 + TB - 1) / TB, TB>>>();

    // 6) proj: [h | s] @ proj_w + b -> g_x
    sgemm_k<0, true, false><<<gB, TB>>>(
        hp, 256, s_in, 256, 256, proj_w, proj_b, nullptr, 0, xp, NS, 256, 512);

    // 7) layernorm -> g_xn
    ln_kernel<<<(NS * 32 + TB - 1) / TB, TB>>>(xp, ln_g, ln_b, xnp);

    // 8) ffn1: gelu(xn @ w1 + b1) -> g_t
    sgemm_k<1, true, false><<<dim3(4, (NS + 127) / 128), TB>>>(
        xnp, 256, xnp, 256, 256, w1, b1, nullptr, 0, tp, NS, DFF, 256);

    // 9) ffn2: g_t @ w2 + b2 + g_x -> out
    sgemm_k<0, true, true><<<gB, TB>>>(
        tp, DFF, tp, DFF, DFF, w2, b2, xp, 256, out, NS, 256, DFF);
}

// round 4
// speedup vs baseline: 1.2632x; 1.2632x over previous
#include <cuda_runtime.h>
#include <cstdint>
#include <math.h>

// Problem constants (fixed by the dataset)
#define NS 100000
#define NE 100000
#define EDG 1600000
#define D 256
#define H 8
#define HD 32
#define FEAT 64
#define DFF 512

#define SCAN_B 1024
#define NBLK ((NS + SCAN_B - 1) / SCAN_B)   // 98

// ---------------- device scratch (no allocations allowed) ----------------
__device__ float g_z[(size_t)NE * D];
__device__ float g_df[(size_t)NS * D];
__device__ float g_h[(size_t)NS * D];
__device__ float g_x[(size_t)NS * D];
__device__ float g_xn[(size_t)NS * D];
__device__ float g_t[(size_t)NS * DFF];
__device__ float g_Wz[D * D];
__device__ float g_Wd[FEAT * D];
__device__ int   g_counts[NS];
__device__ int   g_offsets[NS + 1];
__device__ int   g_cursor[NS];
__device__ int   g_csr_src[EDG];
__device__ int   g_bsum[NBLK];

// ---------------- small helpers ----------------
__device__ __forceinline__ float gelu_tanh(float x) {
    const float c = 0.7978845608028654f;
    float x3 = x * x * x;
    float t = tanhf(c * (x + 0.044715f * x3));
    return 0.5f * x * (1.0f + t);
}

// ---------------- weight repack: (H, K, HD) -> [K, H*HD] ----------------
__global__ void repack_w(const float* __restrict__ w, float* __restrict__ out, int K) {
    int idx = blockIdx.x * blockDim.x + threadIdx.x;
    if (idx >= K * 256) return;
    int k = idx >> 8;
    int n = idx & 255;
    out[idx] = w[(n >> 5) * (K * 32) + k * 32 + (n & 31)];
}

// ---------------- generic fp32 SGEMM: C = act(A @ B + bias) + res ----------------
template <int ACT, bool HAS_BIAS, bool HAS_RES>
__global__ void __launch_bounds__(256) sgemm_k(
    const float* __restrict__ A0, int lda0,
    const float* __restrict__ A1, int lda1, int ksplit,
    const float* __restrict__ B,
    const float* __restrict__ bias,
    const float* __restrict__ res, int ldr,
    float* __restrict__ C,
    int M, int N, int K)
{
    __shared__ float As[8][132];
    __shared__ float Bs[8][128];

    int t  = threadIdx.x;
    int m0 = blockIdx.y * 128;
    int n0 = blockIdx.x * 128;
    int tx = t & 15;
    int ty = t >> 4;

    int a_m = t >> 1;
    int a_k = (t & 1) * 4;
    int b_k = t >> 5;
    int b_n = (t & 31) * 4;

    float acc[8][8];
#pragma unroll
    for (int i = 0; i < 8; i++)
#pragma unroll
        for (int j = 0; j < 8; j++) acc[i][j] = 0.0f;

    for (int k0 = 0; k0 < K; k0 += 8) {
        int gm = m0 + a_m;
        float4 av = make_float4(0.f, 0.f, 0.f, 0.f);
        if (gm < M) {
            int kk = k0 + a_k;
            const float* p = (kk < ksplit)
                                 ? (A0 + (size_t)gm * lda0 + kk)
                                 : (A1 + (size_t)gm * lda1 + (kk - ksplit));
            av = *(const float4*)p;
        }
        As[a_k + 0][a_m] = av.x;
        As[a_k + 1][a_m] = av.y;
        As[a_k + 2][a_m] = av.z;
        As[a_k + 3][a_m] = av.w;

        float4 bv = *(const float4*)(B + (size_t)(k0 + b_k) * N + n0 + b_n);
        *(float4*)&Bs[b_k][b_n] = bv;

        __syncthreads();

#pragma unroll
        for (int kk = 0; kk < 8; kk++) {
            float a[8], b[8];
            *(float4*)(a)     = *(const float4*)&As[kk][ty * 8];
            *(float4*)(a + 4) = *(const float4*)&As[kk][ty * 8 + 4];
            *(float4*)(b)     = *(const float4*)&Bs[kk][tx * 8];
            *(float4*)(b + 4) = *(const float4*)&Bs[kk][tx * 8 + 4];
#pragma unroll
            for (int i = 0; i < 8; i++)
#pragma unroll
                for (int j = 0; j < 8; j++) acc[i][j] += a[i] * b[j];
        }
        __syncthreads();
    }

#pragma unroll
    for (int i = 0; i < 8; i++) {
        int m = m0 + ty * 8 + i;
        if (m >= M) continue;
#pragma unroll
        for (int jv = 0; jv < 2; jv++) {
            int n = n0 + tx * 8 + jv * 4;
            float4 v;
            float* vp = &v.x;
#pragma unroll
            for (int j = 0; j < 4; j++) {
                float val = acc[i][jv * 4 + j];
                if (HAS_BIAS) val += bias[n + j];
                if (ACT == 1) val = gelu_tanh(val);
                vp[j] = val;
            }
            if (HAS_RES) {
                float4 r = *(const float4*)(res + (size_t)m * ldr + n);
                v.x += r.x; v.y += r.y; v.z += r.z; v.w += r.w;
            }
            *(float4*)(C + (size_t)m * N + n) = v;
        }
    }
}

// ---------------- CSR build ----------------
__global__ void zero_counts() {
    int i = blockIdx.x * blockDim.x + threadIdx.x;
    if (i < NS) g_counts[i] = 0;
}
__global__ void hist_kernel(const int* __restrict__ edge_dst) {
    int i = blockIdx.x * blockDim.x + threadIdx.x;
    if (i < EDG) atomicAdd(&g_counts[edge_dst[i]], 1);
}
__global__ void __launch_bounds__(SCAN_B) scan_pass1() {
    __shared__ int ws[32];
    int b = blockIdx.x, t = threadIdx.x;
    int i = b * SCAN_B + t;
    int v = (i < NS) ? g_counts[i] : 0;
#pragma unroll
    for (int o = 16; o; o >>= 1) v += __shfl_xor_sync(0xFFFFFFFFu, v, o);
    if ((t & 31) == 0) ws[t >> 5] = v;
    __syncthreads();
    if (t < 32) {
        int x = ws[t];
#pragma unroll
        for (int o = 16; o; o >>= 1) x += __shfl_xor_sync(0xFFFFFFFFu, x, o);
        if (t == 0) g_bsum[b] = x;
    }
}
__global__ void scan_pass2() {
    __shared__ int sh[128];
    int t = threadIdx.x;
    int orig = (t < NBLK) ? g_bsum[t] : 0;
    sh[t] = orig;
    __syncthreads();
    for (int o = 1; o < 128; o <<= 1) {
        int v = (t >= o) ? sh[t - o] : 0;
        __syncthreads();
        sh[t] += v;
        __syncthreads();
    }
    if (t < NBLK) g_bsum[t] = sh[t] - orig;
}
__global__ void __launch_bounds__(SCAN_B) scan_pass3() {
    __shared__ int ws[32];
    int b = blockIdx.x, t = threadIdx.x;
    int lane = t & 31, w = t >> 5;
    int i = b * SCAN_B + t;
    int v = (i < NS) ? g_counts[i] : 0;
    int x = v;
#pragma unroll
    for (int o = 1; o < 32; o <<= 1) {
        int y = __shfl_up_sync(0xFFFFFFFFu, x, o);
        if (lane >= o) x += y;
    }
    if (lane == 31) ws[w] = x;
    __syncthreads();
    if (w == 0) {
        int sv = ws[lane];
#pragma unroll
        for (int o = 1; o < 32; o <<= 1) {
            int y = __shfl_up_sync(0xFFFFFFFFu, sv, o);
            if (lane >= o) sv += y;
        }
        ws[lane] = sv;
    }
    __syncthreads();
    int incl = x + (w > 0 ? ws[w - 1] : 0) + g_bsum[b];
    if (i < NS) {
        g_offsets[i + 1] = incl;
        g_cursor[i] = incl - v;
    }
    if (b == 0 && t == 0) g_offsets[0] = 0;
}
__global__ void scatter_kernel(const int* __restrict__ edge_src,
                               const int* __restrict__ edge_dst) {
    int i = blockIdx.x * blockDim.x + threadIdx.x;
    if (i >= EDG) return;
    int dst = edge_dst[i];
    int pos = atomicAdd(&g_cursor[dst], 1);
    g_csr_src[pos] = edge_src[i];
}

// ---------------- attention: warp per dst, lane = (head, quarter) ----------------
// lane l -> head l>>2, quarter l&3; each lane owns 8 contiguous z/df floats.
// Per edge: 2 float4 loads, 2 shuffles (4-lane dot reduce), 2 exp, online softmax.
__global__ void __launch_bounds__(256) attn_kernel() {
    int gw = (blockIdx.x * blockDim.x + threadIdx.x) >> 5;
    if (gw >= NS) return;
    int lane = threadIdx.x & 31;
    int off = (lane >> 2) * 32 + (lane & 3) * 8;  // base column for this lane

    int beg = g_offsets[gw];
    int end = g_offsets[gw + 1];

    const float* dfp = g_df + (size_t)gw * 256 + off;
    float4 d0 = *(const float4*)(dfp);
    float4 d1 = *(const float4*)(dfp + 4);

    float m = -1e30f, den = 0.0f;
    float4 a0 = make_float4(0.f, 0.f, 0.f, 0.f);
    float4 a1 = make_float4(0.f, 0.f, 0.f, 0.f);

    int e = beg;
    // 2x unrolled main loop for memory-level parallelism
    for (; e + 2 <= end; e += 2) {
        int s0 = __ldg(&g_csr_src[e]);
        int s1 = __ldg(&g_csr_src[e + 1]);
        const float* zp0 = g_z + (size_t)s0 * 256 + off;
        const float* zp1 = g_z + (size_t)s1 * 256 + off;
        float4 x0 = __ldg((const float4*)zp0);
        float4 x1 = __ldg((const float4*)(zp0 + 4));
        float4 y0 = __ldg((const float4*)zp1);
        float4 y1 = __ldg((const float4*)(zp1 + 4));

        float sa = x0.x * d0.x + x0.y * d0.y + x0.z * d0.z + x0.w * d0.w
                 + x1.x * d1.x + x1.y * d1.y + x1.z * d1.z + x1.w * d1.w;
        float sb = y0.x * d0.x + y0.y * d0.y + y0.z * d0.z + y0.w * d0.w
                 + y1.x * d1.x + y1.y * d1.y + y1.z * d1.z + y1.w * d1.w;
        sa += __shfl_xor_sync(0xFFFFFFFFu, sa, 1);
        sb += __shfl_xor_sync(0xFFFFFFFFu, sb, 1);
        sa += __shfl_xor_sync(0xFFFFFFFFu, sa, 2);
        sb += __shfl_xor_sync(0xFFFFFFFFu, sb, 2);

        // edge A
        {
            float mn = fmaxf(m, sa);
            float sc = __expf(m - mn);
            float w  = __expf(sa - mn);
            den = den * sc + w;
            a0.x = a0.x * sc + w * x0.x; a0.y = a0.y * sc + w * x0.y;
            a0.z = a0.z * sc + w * x0.z; a0.w = a0.w * sc + w * x0.w;
            a1.x = a1.x * sc + w * x1.x; a1.y = a1.y * sc + w * x1.y;
            a1.z = a1.z * sc + w * x1.z; a1.w = a1.w * sc + w * x1.w;
            m = mn;
        }
        // edge B
        {
            float mn = fmaxf(m, sb);
            float sc = __expf(m - mn);
            float w  = __expf(sb - mn);
            den = den * sc + w;
            a0.x = a0.x * sc + w * y0.x; a0.y = a0.y * sc + w * y0.y;
            a0.z = a0.z * sc + w * y0.z; a0.w = a0.w * sc + w * y0.w;
            a1.x = a1.x * sc + w * y1.x; a1.y = a1.y * sc + w * y1.y;
            a1.z = a1.z * sc + w * y1.z; a1.w = a1.w * sc + w * y1.w;
            m = mn;
        }
    }
    // tail
    for (; e < end; e++) {
        int s0 = __ldg(&g_csr_src[e]);
        const float* zp0 = g_z + (size_t)s0 * 256 + off;
        float4 x0 = __ldg((const float4*)zp0);
        float4 x1 = __ldg((const float4*)(zp0 + 4));
        float sa = x0.x * d0.x + x0.y * d0.y + x0.z * d0.z + x0.w * d0.w
                 + x1.x * d1.x + x1.y * d1.y + x1.z * d1.z + x1.w * d1.w;
        sa += __shfl_xor_sync(0xFFFFFFFFu, sa, 1);
        sa += __shfl_xor_sync(0xFFFFFFFFu, sa, 2);
        float mn = fmaxf(m, sa);
        float sc = __expf(m - mn);
        float w  = __expf(sa - mn);
        den = den * sc + w;
        a0.x = a0.x * sc + w * x0.x; a0.y = a0.y * sc + w * x0.y;
        a0.z = a0.z * sc + w * x0.z; a0.w = a0.w * sc + w * x0.w;
        a1.x = a1.x * sc + w * x1.x; a1.y = a1.y * sc + w * x1.y;
        a1.z = a1.z * sc + w * x1.z; a1.w = a1.w * sc + w * x1.w;
        m = mn;
    }

    float inv = 1.0f / den;
    float v[8];
    v[0] = a0.x * inv; v[1] = a0.y * inv; v[2] = a0.z * inv; v[3] = a0.w * inv;
    v[4] = a1.x * inv; v[5] = a1.y * inv; v[6] = a1.z * inv; v[7] = a1.w * inv;
#pragma unroll
    for (int i = 0; i < 8; i++)
        v[i] = (v[i] > 0.0f) ? v[i] : expm1f(v[i]);  // ELU(alpha=1)

    float* hp = g_h + (size_t)gw * 256 + off;
    *(float4*)(hp)     = make_float4(v[0], v[1], v[2], v[3]);
    *(float4*)(hp + 4) = make_float4(v[4], v[5], v[6], v[7]);
}

// ---------------- layernorm: one warp per row ----------------
__global__ void ln_kernel(const float* __restrict__ x,
                          const float* __restrict__ gam,
                          const float* __restrict__ bet,
                          float* __restrict__ y) {
    int row = (blockIdx.x * blockDim.x + threadIdx.x) >> 5;
    if (row >= NS) return;
    int lane = threadIdx.x & 31;
    const float* xp = x + (size_t)row * 256;
    float v[8];
    float s = 0.0f, s2 = 0.0f;
#pragma unroll
    for (int r = 0; r < 8; r++) {
        v[r] = xp[r * 32 + lane];
        s += v[r];
        s2 += v[r] * v[r];
    }
#pragma unroll
    for (int off = 16; off > 0; off >>= 1) {
        s  += __shfl_xor_sync(0xFFFFFFFFu, s, off);
        s2 += __shfl_xor_sync(0xFFFFFFFFu, s2, off);
    }
    float mean = s * (1.0f / 256.0f);
    float var = s2 * (1.0f / 256.0f) - mean * mean;
    float inv = rsqrtf(var + 1e-6f);
    float* yp = y + (size_t)row * 256;
#pragma unroll
    for (int r = 0; r < 8; r++) {
        int c = r * 32 + lane;
        yp[c] = (v[r] - mean) * inv * gam[c] + bet[c];
    }
}

// ---------------- launch ----------------
extern "C" void kernel_launch(void* const* d_in, const int* in_sizes, int n_in,
                              void* d_out, int out_size) {
    const float* s_in      = (const float*)d_in[0];
    const float* e_in      = (const float*)d_in[1];
    const float* dst_feat  = (const float*)d_in[2];
    const float* fc_w      = (const float*)d_in[3];
    const float* dstfeat_w = (const float*)d_in[4];
    const float* proj_w    = (const float*)d_in[5];
    const float* proj_b    = (const float*)d_in[6];
    const float* ln_g      = (const float*)d_in[7];
    const float* ln_b      = (const float*)d_in[8];
    const float* w1        = (const float*)d_in[9];
    const float* b1        = (const float*)d_in[10];
    const float* w2        = (const float*)d_in[11];
    const float* b2        = (const float*)d_in[12];
    const int*   edge_src  = (const int*)d_in[13];
    const int*   edge_dst  = (const int*)d_in[14];
    float* out = (float*)d_out;

    float *zp, *dfp, *hp, *xp, *xnp, *tp, *wzp, *wdp;
    cudaGetSymbolAddress((void**)&zp,  g_z);
    cudaGetSymbolAddress((void**)&dfp, g_df);
    cudaGetSymbolAddress((void**)&hp,  g_h);
    cudaGetSymbolAddress((void**)&xp,  g_x);
    cudaGetSymbolAddress((void**)&xnp, g_xn);
    cudaGetSymbolAddress((void**)&tp,  g_t);
    cudaGetSymbolAddress((void**)&wzp, g_Wz);
    cudaGetSymbolAddress((void**)&wdp, g_Wd);

    const int TB = 256;
    dim3 gB(2, (NS + 127) / 128);

    // 1) repack per-head weights into plain [K, 256] matrices
    repack_w<<<(D * 256 + TB - 1) / TB, TB>>>(fc_w, wzp, D);
    repack_w<<<(FEAT * 256 + TB - 1) / TB, TB>>>(dstfeat_w, wdp, FEAT);

    // 2) z = e @ Wz  [NE,256]
    sgemm_k<0, false, false><<<dim3(2, (NE + 127) / 128), TB>>>(
        e_in, D, e_in, D, D, wzp, nullptr, nullptr, 0, zp, NE, 256, D);

    // 3) df = dst_feat @ Wd  [NS,256]
    sgemm_k<0, false, false><<<gB, TB>>>(
        dst_feat, FEAT, dst_feat, FEAT, FEAT, wdp, nullptr, nullptr, 0, dfp, NS, 256, FEAT);

    // 4) CSR build by dst (parallel decoupled scan)
    zero_counts<<<(NS + TB - 1) / TB, TB>>>();
    hist_kernel<<<(EDG + TB - 1) / TB, TB>>>(edge_dst);
    scan_pass1<<<NBLK, SCAN_B>>>();
    scan_pass2<<<1, 128>>>();
    scan_pass3<<<NBLK, SCAN_B>>>();
    scatter_kernel<<<(EDG + TB - 1) / TB, TB>>>(edge_src, edge_dst);

    // 5) attention + ELU -> g_h
    attn_kernel<<<(NS * 32 + TB - 1) / TB, TB>>>();

    // 6) proj: [h | s] @ proj_w + b -> g_x
    sgemm_k<0, true, false><<<gB, TB>>>(
        hp, 256, s_in, 256, 256, proj_w, proj_b, nullptr, 0, xp, NS, 256, 512);

    // 7) layernorm -> g_xn
    ln_kernel<<<(NS * 32 + TB - 1) / TB, TB>>>(xp, ln_g, ln_b, xnp);

    // 8) ffn1: gelu(xn @ w1 + b1) -> g_t
    sgemm_k<1, true, false><<<dim3(4, (NS + 127) / 128), TB>>>(
        xnp, 256, xnp, 256, 256, w1, b1, nullptr, 0, tp, NS, DFF, 256);

    // 9) ffn2: g_t @ w2 + b2 + g_x -> out
    sgemm_k<0, true, true><<<gB, TB>>>(
        tp, DFF, tp, DFF, DFF, w2, b2, xp, 256, out, NS, 256, DFF);
}